// round 2
// baseline (speedup 1.0000x reference)
#include <cuda_runtime.h>
#include <math.h>
#include <stdint.h>

// Problem constants
#define D    1024
#define NH   16
#define DKH  64
#define TSEQ 2048
#define BSZ  4
#define MTOT (BSZ * TSEQ)   // 8192

// Static scratch (allocation-free rule): Q, K, V projections and attention output Y.
__device__ float g_Q[MTOT * D];
__device__ float g_K[MTOT * D];
__device__ float g_V[MTOT * D];
__device__ float g_Y[MTOT * D];

// Scratch selector so the host never needs cudaGetSymbolAddress.
__device__ __forceinline__ float* scratch_ptr(int which) {
    switch (which) {
        case 0: return g_Q;
        case 1: return g_K;
        case 2: return g_V;
        default: return g_Y;
    }
}

// ---------------------------------------------------------------------------
// GEMM (NT): C[M,N] = A[M,K] * B[N,K]^T   (both row-major, fp32)
// BM=128, BN=128, BK=16, 256 threads, 8x8 micro-tile per thread.
// a_sel/c_sel: -1 -> use pointer arg; >=0 -> use scratch_ptr(sel).
// ---------------------------------------------------------------------------
__global__ __launch_bounds__(256) void gemm_nt_kernel(
    const float* __restrict__ Ain, const float* __restrict__ B,
    float* __restrict__ Cout, int a_sel, int c_sel, int M, int N, int K)
{
    const float* A = (a_sel >= 0) ? scratch_ptr(a_sel) : Ain;
    float*       C = (c_sel >= 0) ? scratch_ptr(c_sel) : Cout;

    const int BM = 128, BN = 128, BK = 16;
    __shared__ __align__(16) float As[BK][BM + 4];  // transposed A tile: As[kk][row]
    __shared__ __align__(16) float Bs[BK][BN + 4];  // transposed B tile: Bs[kk][col]

    const int tid = threadIdx.x;
    const int tr = tid >> 4;        // 0..15
    const int tc = tid & 15;        // 0..15
    const int bm = blockIdx.y * BM;
    const int bn = blockIdx.x * BN;

    const int lrow = tid >> 2;            // 0..63
    const int lc4  = (tid & 3) << 2;      // 0,4,8,12

    float acc[8][8];
    #pragma unroll
    for (int i = 0; i < 8; i++)
        #pragma unroll
        for (int j = 0; j < 8; j++) acc[i][j] = 0.f;

    for (int k0 = 0; k0 < K; k0 += BK) {
        #pragma unroll
        for (int p = 0; p < 2; p++) {
            int r = lrow + p * 64;
            float4 v = *(const float4*)(A + (size_t)(bm + r) * K + k0 + lc4);
            As[lc4 + 0][r] = v.x; As[lc4 + 1][r] = v.y;
            As[lc4 + 2][r] = v.z; As[lc4 + 3][r] = v.w;
        }
        #pragma unroll
        for (int p = 0; p < 2; p++) {
            int r = lrow + p * 64;
            float4 v = *(const float4*)(B + (size_t)(bn + r) * K + k0 + lc4);
            Bs[lc4 + 0][r] = v.x; Bs[lc4 + 1][r] = v.y;
            Bs[lc4 + 2][r] = v.z; Bs[lc4 + 3][r] = v.w;
        }
        __syncthreads();

        #pragma unroll
        for (int kk = 0; kk < BK; kk++) {
            float a[8], b[8];
            *(float4*)&a[0] = *(const float4*)&As[kk][tr * 8];
            *(float4*)&a[4] = *(const float4*)&As[kk][tr * 8 + 4];
            *(float4*)&b[0] = *(const float4*)&Bs[kk][tc * 8];
            *(float4*)&b[4] = *(const float4*)&Bs[kk][tc * 8 + 4];
            #pragma unroll
            for (int i = 0; i < 8; i++)
                #pragma unroll
                for (int j = 0; j < 8; j++)
                    acc[i][j] += a[i] * b[j];
        }
        __syncthreads();
    }

    #pragma unroll
    for (int i = 0; i < 8; i++) {
        float* crow = C + (size_t)(bm + tr * 8 + i) * N + bn + tc * 8;
        *(float4*)(crow)     = *(float4*)&acc[i][0];
        *(float4*)(crow + 4) = *(float4*)&acc[i][4];
    }
}

// ---------------------------------------------------------------------------
// Flash attention, fp32, online softmax.
// Grid: (T/64, NH, BSZ). Block: 256 threads (16x16), 4x4 micro-tile.
// smem (dynamic): Qs[64][68] transposed, Ks[64][68] transposed (reused as
// P^T after scores), Vs[64][64] row-major. 51200 bytes.
// Reads g_Q/g_K/g_V, writes g_Y directly (no host symbol lookup needed).
// ---------------------------------------------------------------------------
#define QK_PAD 68
#define ATTN_SMEM_BYTES ((2 * 64 * QK_PAD + 64 * 64) * 4)

__global__ __launch_bounds__(256) void attn_kernel()
{
    extern __shared__ __align__(16) float sm[];
    float* Qs = sm;                       // [64][QK_PAD], Qs[kk*QK_PAD + row]
    float* Ks = sm + 64 * QK_PAD;         // [64][QK_PAD]; reused as P^T[c][r]
    float* Vs = sm + 2 * 64 * QK_PAD;     // [64][64],     Vs[c*64 + d]

    const int tid = threadIdx.x;
    const int tr = tid >> 4;   // 0..15 -> rows tr*4..+3
    const int tc = tid & 15;   // 0..15 -> cols/dims tc*4..+3
    const int q0 = blockIdx.x * 64;
    const int h  = blockIdx.y;
    const int b  = blockIdx.z;

    const float* Qbase = g_Q + (size_t)b * TSEQ * D + h * DKH;
    const float* Kbase = g_K + (size_t)b * TSEQ * D + h * DKH;
    const float* Vbase = g_V + (size_t)b * TSEQ * D + h * DKH;

    // Load Q tile [64 rows x 64 cols], transposed into Qs[kk][row].
    #pragma unroll
    for (int p = 0; p < 4; p++) {
        int idx = tid + p * 256;
        int row = idx >> 4;
        int c4  = (idx & 15) << 2;
        float4 v = *(const float4*)(Qbase + (size_t)(q0 + row) * D + c4);
        Qs[(c4 + 0) * QK_PAD + row] = v.x;
        Qs[(c4 + 1) * QK_PAD + row] = v.y;
        Qs[(c4 + 2) * QK_PAD + row] = v.z;
        Qs[(c4 + 3) * QK_PAD + row] = v.w;
    }

    float m_i[4], l_i[4], o[4][4];
    #pragma unroll
    for (int i = 0; i < 4; i++) {
        m_i[i] = -INFINITY; l_i[i] = 0.f;
        #pragma unroll
        for (int j = 0; j < 4; j++) o[i][j] = 0.f;
    }

    const float scale = 0.125f;  // 1/sqrt(64)

    for (int s0 = 0; s0 < TSEQ; s0 += 64) {
        __syncthreads();  // Q visible (iter 0); prior PV reads of Ks/Vs done (iter >0)

        // Load K chunk transposed, V chunk row-major.
        #pragma unroll
        for (int p = 0; p < 4; p++) {
            int idx = tid + p * 256;
            int row = idx >> 4;
            int c4  = (idx & 15) << 2;
            float4 kv = *(const float4*)(Kbase + (size_t)(s0 + row) * D + c4);
            Ks[(c4 + 0) * QK_PAD + row] = kv.x;
            Ks[(c4 + 1) * QK_PAD + row] = kv.y;
            Ks[(c4 + 2) * QK_PAD + row] = kv.z;
            Ks[(c4 + 3) * QK_PAD + row] = kv.w;
            float4 vv = *(const float4*)(Vbase + (size_t)(s0 + row) * D + c4);
            *(float4*)&Vs[row * 64 + c4] = vv;
        }
        __syncthreads();

        // Scores S = Q K^T (4x4 micro-tile per thread).
        float s[4][4];
        #pragma unroll
        for (int i = 0; i < 4; i++)
            #pragma unroll
            for (int j = 0; j < 4; j++) s[i][j] = 0.f;

        #pragma unroll 8
        for (int kk = 0; kk < DKH; kk++) {
            float4 qa = *(const float4*)&Qs[kk * QK_PAD + tr * 4];
            float4 kb = *(const float4*)&Ks[kk * QK_PAD + tc * 4];
            float a[4] = {qa.x, qa.y, qa.z, qa.w};
            float bb[4] = {kb.x, kb.y, kb.z, kb.w};
            #pragma unroll
            for (int i = 0; i < 4; i++)
                #pragma unroll
                for (int j = 0; j < 4; j++)
                    s[i][j] += a[i] * bb[j];
        }

        // Online softmax update (per row: reduce over 16 tc lanes via shfl).
        #pragma unroll
        for (int i = 0; i < 4; i++) {
            float rmax = s[i][0];
            #pragma unroll
            for (int j = 1; j < 4; j++) rmax = fmaxf(rmax, s[i][j]);
            rmax *= scale;
            #pragma unroll
            for (int off = 8; off > 0; off >>= 1)
                rmax = fmaxf(rmax, __shfl_xor_sync(0xffffffffu, rmax, off));

            float mnew = fmaxf(m_i[i], rmax);
            float corr = __expf(m_i[i] - mnew);
            m_i[i] = mnew;

            float rsum = 0.f;
            #pragma unroll
            for (int j = 0; j < 4; j++) {
                float p = __expf(s[i][j] * scale - mnew);
                s[i][j] = p;
                rsum += p;
            }
            #pragma unroll
            for (int off = 8; off > 0; off >>= 1)
                rsum += __shfl_xor_sync(0xffffffffu, rsum, off);

            l_i[i] = l_i[i] * corr + rsum;
            #pragma unroll
            for (int j = 0; j < 4; j++) o[i][j] *= corr;
        }

        __syncthreads();  // everyone done reading Ks (scores)

        // Store P transposed into Ks: P^T[c][r].
        #pragma unroll
        for (int j = 0; j < 4; j++) {
            float4 pv = make_float4(s[0][j], s[1][j], s[2][j], s[3][j]);
            *(float4*)&Ks[(tc * 4 + j) * QK_PAD + tr * 4] = pv;
        }
        __syncthreads();

        // O += P V  (thread owns rows tr*4.., dims tc*4..)
        #pragma unroll 8
        for (int c = 0; c < 64; c++) {
            float4 pr = *(const float4*)&Ks[c * QK_PAD + tr * 4];
            float4 vv = *(const float4*)&Vs[c * 64 + tc * 4];
            float p[4] = {pr.x, pr.y, pr.z, pr.w};
            float v[4] = {vv.x, vv.y, vv.z, vv.w};
            #pragma unroll
            for (int i = 0; i < 4; i++)
                #pragma unroll
                for (int j = 0; j < 4; j++)
                    o[i][j] += p[i] * v[j];
        }
    }

    // Epilogue: normalize and write Y[b*T + q, h*64 + d].
    #pragma unroll
    for (int i = 0; i < 4; i++) {
        float inv = 1.f / l_i[i];
        float4 r = make_float4(o[i][0] * inv, o[i][1] * inv,
                               o[i][2] * inv, o[i][3] * inv);
        *(float4*)(g_Y + (size_t)((size_t)b * TSEQ + q0 + tr * 4 + i) * D
                       + h * DKH + tc * 4) = r;
    }
}

// ---------------------------------------------------------------------------
extern "C" void kernel_launch(void* const* d_in, const int* in_sizes, int n_in,
                              void* d_out, int out_size)
{
    const float* X  = (const float*)d_in[0];
    const float* Wq = (const float*)d_in[1];
    const float* Wk = (const float*)d_in[2];
    const float* Wv = (const float*)d_in[3];
    const float* Wo = (const float*)d_in[4];
    float* out = (float*)d_out;

    static int smem_set = 0;
    if (!smem_set) {
        cudaFuncSetAttribute(attn_kernel,
                             cudaFuncAttributeMaxDynamicSharedMemorySize,
                             ATTN_SMEM_BYTES);
        smem_set = 1;
    }

    dim3 gemm_grid(D / 128, MTOT / 128);   // (8, 64)
    // Projections: A = X (external), C = scratch 0/1/2
    gemm_nt_kernel<<<gemm_grid, 256>>>(X, Wq, nullptr, -1, 0, MTOT, D, D);
    gemm_nt_kernel<<<gemm_grid, 256>>>(X, Wk, nullptr, -1, 1, MTOT, D, D);
    gemm_nt_kernel<<<gemm_grid, 256>>>(X, Wv, nullptr, -1, 2, MTOT, D, D);

    dim3 attn_grid(TSEQ / 64, NH, BSZ);    // (32, 16, 4)
    attn_kernel<<<attn_grid, 256, ATTN_SMEM_BYTES>>>();

    // Output projection: A = scratch 3 (Y), C = d_out
    gemm_nt_kernel<<<gemm_grid, 256>>>(nullptr, Wo, out, 3, -1, MTOT, D, D);
}

// round 4
// speedup vs baseline: 2.8718x; 2.8718x over previous
#include <cuda_runtime.h>
#include <math.h>
#include <stdint.h>

// Problem constants
#define D    1024
#define NH   16
#define DKH  64
#define TSEQ 2048
#define BSZ  4
#define MTOT (BSZ * TSEQ)   // 8192

// Static scratch (allocation-free rule)
__device__ float g_Q[MTOT * D];
__device__ float g_K[MTOT * D];
__device__ float g_V[MTOT * D];
__device__ float g_Y[MTOT * D];

__device__ __forceinline__ float* scratch_ptr(int which) {
    switch (which) {
        case 0: return g_Q;
        case 1: return g_K;
        case 2: return g_V;
        default: return g_Y;
    }
}

// ---------------------------------------------------------------------------
// mma.sync tf32 helpers (portable Blackwell/Hopper/Ampere tensor-core path)
// ---------------------------------------------------------------------------
__device__ __forceinline__ uint32_t tf32b(float x) {
    uint32_t y;
    asm("cvt.rna.tf32.f32 %0, %1;" : "=r"(y) : "f"(x));
    return y;
}

__device__ __forceinline__ void mma_tf32(
    float c[4], uint32_t a0, uint32_t a1, uint32_t a2, uint32_t a3,
    uint32_t b0, uint32_t b1)
{
    asm volatile(
        "mma.sync.aligned.m16n8k8.row.col.f32.tf32.tf32.f32 "
        "{%0,%1,%2,%3}, {%4,%5,%6,%7}, {%8,%9}, {%0,%1,%2,%3};"
        : "+f"(c[0]), "+f"(c[1]), "+f"(c[2]), "+f"(c[3])
        : "r"(a0), "r"(a1), "r"(a2), "r"(a3), "r"(b0), "r"(b1));
}

__device__ __forceinline__ float4 tf32_f4(float4 v) {
    float4 w;
    w.x = __uint_as_float(tf32b(v.x));
    w.y = __uint_as_float(tf32b(v.y));
    w.z = __uint_as_float(tf32b(v.z));
    w.w = __uint_as_float(tf32b(v.w));
    return w;
}

// ---------------------------------------------------------------------------
// tf32 mma NT-GEMM: C[M,N] = A[M,K] * B[N,K]^T, M=8192, N=K=1024.
// BM=128, BN=128, BK=16. 256 threads = 8 warps; warp tile 64x32
// (warp_m in {0,1} x 64 rows, warp_n in {0..3} x 32 cols).
// Smem: As[m][20], Bs[n][20] (16 k-floats + 4 pad -> conflict-free frags).
// Double-buffered smem with register prefetch.
// ---------------------------------------------------------------------------
#define GSTRIDE 20

__global__ __launch_bounds__(256) void mma_gemm(
    const float* __restrict__ Ain, const float* __restrict__ Bw,
    float* __restrict__ Cout, int a_sel, int c_sel)
{
    const float* A = (a_sel >= 0) ? scratch_ptr(a_sel) : Ain;
    float*       C = (c_sel >= 0) ? scratch_ptr(c_sel) : Cout;

    __shared__ __align__(16) float As[2][128 * GSTRIDE];
    __shared__ __align__(16) float Bs[2][128 * GSTRIDE];

    const int tid  = threadIdx.x;
    const int wid  = tid >> 5;
    const int lane = tid & 31;
    const int gid  = lane >> 2;     // 0..7
    const int tig  = lane & 3;      // 0..3
    const int wm   = (wid >> 2) * 64;
    const int wn   = (wid & 3) * 32;
    const int bm   = blockIdx.y * 128;
    const int bn   = blockIdx.x * 128;

    const int row = tid >> 2;           // 0..63
    const int jc  = (tid & 3) * 4;      // 0,4,8,12

    float acc[4][4][4];
    #pragma unroll
    for (int mt = 0; mt < 4; mt++)
        #pragma unroll
        for (int nt = 0; nt < 4; nt++)
            #pragma unroll
            for (int e = 0; e < 4; e++) acc[mt][nt][e] = 0.f;

    float4 pa0, pa1, pb0, pb1;

    // prologue: tile 0
    {
        pa0 = *(const float4*)(A  + (size_t)(bm + row)      * D + jc);
        pa1 = *(const float4*)(A  + (size_t)(bm + row + 64) * D + jc);
        pb0 = *(const float4*)(Bw + (size_t)(bn + row)      * D + jc);
        pb1 = *(const float4*)(Bw + (size_t)(bn + row + 64) * D + jc);
        *(float4*)&As[0][(row)      * GSTRIDE + jc] = tf32_f4(pa0);
        *(float4*)&As[0][(row + 64) * GSTRIDE + jc] = tf32_f4(pa1);
        *(float4*)&Bs[0][(row)      * GSTRIDE + jc] = tf32_f4(pb0);
        *(float4*)&Bs[0][(row + 64) * GSTRIDE + jc] = tf32_f4(pb1);
    }
    __syncthreads();

    int buf = 0;
    #pragma unroll 1
    for (int kt = 0; kt < D / 16; kt++) {
        if (kt < D / 16 - 1) {
            const int k0 = (kt + 1) * 16;
            pa0 = *(const float4*)(A  + (size_t)(bm + row)      * D + k0 + jc);
            pa1 = *(const float4*)(A  + (size_t)(bm + row + 64) * D + k0 + jc);
            pb0 = *(const float4*)(Bw + (size_t)(bn + row)      * D + k0 + jc);
            pb1 = *(const float4*)(Bw + (size_t)(bn + row + 64) * D + k0 + jc);
        }

        const float* as = As[buf];
        const float* bs = Bs[buf];
        #pragma unroll
        for (int ks = 0; ks < 2; ks++) {
            const int kb = ks * 8;
            uint32_t af[4][4];
            #pragma unroll
            for (int mt = 0; mt < 4; mt++) {
                const int m = wm + mt * 16 + gid;
                af[mt][0] = __float_as_uint(as[(m)     * GSTRIDE + kb + tig]);
                af[mt][1] = __float_as_uint(as[(m + 8) * GSTRIDE + kb + tig]);
                af[mt][2] = __float_as_uint(as[(m)     * GSTRIDE + kb + tig + 4]);
                af[mt][3] = __float_as_uint(as[(m + 8) * GSTRIDE + kb + tig + 4]);
            }
            uint32_t bf[4][2];
            #pragma unroll
            for (int nt = 0; nt < 4; nt++) {
                const int n = wn + nt * 8 + gid;
                bf[nt][0] = __float_as_uint(bs[n * GSTRIDE + kb + tig]);
                bf[nt][1] = __float_as_uint(bs[n * GSTRIDE + kb + tig + 4]);
            }
            #pragma unroll
            for (int mt = 0; mt < 4; mt++)
                #pragma unroll
                for (int nt = 0; nt < 4; nt++)
                    mma_tf32(acc[mt][nt], af[mt][0], af[mt][1], af[mt][2], af[mt][3],
                             bf[nt][0], bf[nt][1]);
        }

        if (kt < D / 16 - 1) {
            const int nb = buf ^ 1;
            *(float4*)&As[nb][(row)      * GSTRIDE + jc] = tf32_f4(pa0);
            *(float4*)&As[nb][(row + 64) * GSTRIDE + jc] = tf32_f4(pa1);
            *(float4*)&Bs[nb][(row)      * GSTRIDE + jc] = tf32_f4(pb0);
            *(float4*)&Bs[nb][(row + 64) * GSTRIDE + jc] = tf32_f4(pb1);
            __syncthreads();
            buf = nb;
        }
    }

    // epilogue
    #pragma unroll
    for (int mt = 0; mt < 4; mt++) {
        #pragma unroll
        for (int nt = 0; nt < 4; nt++) {
            const int r0 = bm + wm + mt * 16 + gid;
            const int cc = bn + wn + nt * 8 + 2 * tig;
            float2 v0 = make_float2(acc[mt][nt][0], acc[mt][nt][1]);
            float2 v1 = make_float2(acc[mt][nt][2], acc[mt][nt][3]);
            *(float2*)(C + (size_t)r0 * D + cc)       = v0;
            *(float2*)(C + (size_t)(r0 + 8) * D + cc) = v1;
        }
    }
}

// ---------------------------------------------------------------------------
// Flash attention with mma.sync tf32.
// Grid (T/64, NH, BSZ), 128 threads = 4 warps. Warp w owns q-rows [w*16, w*16+16).
// S = Q K^T (scale folded into Q), online softmax in registers,
// P stored to smem (aliasing K tile) for re-fragmentation, O += P V.
// Smem: Qs[64][68], Ks/Ps[64][68], Vs[64][72]. 53248 bytes dynamic.
// ---------------------------------------------------------------------------
#define AP 68
#define VP 72
#define ATTN_SMEM_BYTES ((2 * 64 * AP + 64 * VP) * 4)

__global__ __launch_bounds__(128) void attn_mma()
{
    extern __shared__ __align__(16) float sm[];
    float* Qs = sm;                 // [64][AP]
    float* Ks = sm + 64 * AP;       // [64][AP]; reused as Ps
    float* Vs = sm + 2 * 64 * AP;   // [64][VP]

    const int tid  = threadIdx.x;
    const int wid  = tid >> 5;
    const int lane = tid & 31;
    const int gid  = lane >> 2;
    const int tig  = lane & 3;
    const int wq   = wid * 16;
    const int q0   = blockIdx.x * 64;
    const int h    = blockIdx.y;
    const int b    = blockIdx.z;

    const float* Qb = g_Q + (size_t)b * TSEQ * D + h * DKH;
    const float* Kb = g_K + (size_t)b * TSEQ * D + h * DKH;
    const float* Vb = g_V + (size_t)b * TSEQ * D + h * DKH;

    // Load Q once: fold softmax scale (1/8) and convert tf32.
    #pragma unroll
    for (int p = 0; p < 8; p++) {
        int idx = tid + p * 128;
        int r = idx >> 4;
        int c4 = (idx & 15) * 4;
        float4 v = *(const float4*)(Qb + (size_t)(q0 + r) * D + c4);
        v.x *= 0.125f; v.y *= 0.125f; v.z *= 0.125f; v.w *= 0.125f;
        *(float4*)&Qs[r * AP + c4] = tf32_f4(v);
    }

    float O[8][4];
    #pragma unroll
    for (int nt = 0; nt < 8; nt++)
        #pragma unroll
        for (int e = 0; e < 4; e++) O[nt][e] = 0.f;
    float m0 = -INFINITY, m1 = -INFINITY, l0 = 0.f, l1 = 0.f;

    #pragma unroll 1
    for (int s0 = 0; s0 < TSEQ; s0 += 64) {
        __syncthreads();   // prior PV done reading Ps/Vs; Qs ready (iter 0)

        // Load K, V chunk (tf32).
        #pragma unroll
        for (int p = 0; p < 8; p++) {
            int idx = tid + p * 128;
            int r = idx >> 4;
            int c4 = (idx & 15) * 4;
            float4 kv = *(const float4*)(Kb + (size_t)(s0 + r) * D + c4);
            *(float4*)&Ks[r * AP + c4] = tf32_f4(kv);
            float4 vv = *(const float4*)(Vb + (size_t)(s0 + r) * D + c4);
            *(float4*)&Vs[r * VP + c4] = tf32_f4(vv);
        }
        __syncthreads();

        // S = Q K^T : warp tile 16 x 64, ntiles=8, ksteps=8.
        float S[8][4];
        #pragma unroll
        for (int nt = 0; nt < 8; nt++)
            #pragma unroll
            for (int e = 0; e < 4; e++) S[nt][e] = 0.f;

        #pragma unroll
        for (int ks = 0; ks < 8; ks++) {
            const int kb = ks * 8;
            uint32_t a0 = __float_as_uint(Qs[(wq + gid)     * AP + kb + tig]);
            uint32_t a1 = __float_as_uint(Qs[(wq + gid + 8) * AP + kb + tig]);
            uint32_t a2 = __float_as_uint(Qs[(wq + gid)     * AP + kb + tig + 4]);
            uint32_t a3 = __float_as_uint(Qs[(wq + gid + 8) * AP + kb + tig + 4]);
            #pragma unroll
            for (int nt = 0; nt < 8; nt++) {
                const int n = nt * 8 + gid;
                uint32_t b0 = __float_as_uint(Ks[n * AP + kb + tig]);
                uint32_t b1 = __float_as_uint(Ks[n * AP + kb + tig + 4]);
                mma_tf32(S[nt], a0, a1, a2, a3, b0, b1);
            }
        }

        // Online softmax. Thread owns rows (wq+gid) [c0,c1] and (wq+gid+8) [c2,c3],
        // cols nt*8 + 2*tig(+1). Row reduction = local over nt + shfl over tig quad.
        float rmax0 = -INFINITY, rmax1 = -INFINITY;
        #pragma unroll
        for (int nt = 0; nt < 8; nt++) {
            rmax0 = fmaxf(rmax0, fmaxf(S[nt][0], S[nt][1]));
            rmax1 = fmaxf(rmax1, fmaxf(S[nt][2], S[nt][3]));
        }
        rmax0 = fmaxf(rmax0, __shfl_xor_sync(0xffffffffu, rmax0, 1));
        rmax0 = fmaxf(rmax0, __shfl_xor_sync(0xffffffffu, rmax0, 2));
        rmax1 = fmaxf(rmax1, __shfl_xor_sync(0xffffffffu, rmax1, 1));
        rmax1 = fmaxf(rmax1, __shfl_xor_sync(0xffffffffu, rmax1, 2));

        const float mn0 = fmaxf(m0, rmax0);
        const float mn1 = fmaxf(m1, rmax1);
        const float cr0 = __expf(m0 - mn0);
        const float cr1 = __expf(m1 - mn1);
        m0 = mn0; m1 = mn1;

        float rs0 = 0.f, rs1 = 0.f;
        #pragma unroll
        for (int nt = 0; nt < 8; nt++) {
            S[nt][0] = __expf(S[nt][0] - mn0); rs0 += S[nt][0];
            S[nt][1] = __expf(S[nt][1] - mn0); rs0 += S[nt][1];
            S[nt][2] = __expf(S[nt][2] - mn1); rs1 += S[nt][2];
            S[nt][3] = __expf(S[nt][3] - mn1); rs1 += S[nt][3];
        }
        rs0 += __shfl_xor_sync(0xffffffffu, rs0, 1);
        rs0 += __shfl_xor_sync(0xffffffffu, rs0, 2);
        rs1 += __shfl_xor_sync(0xffffffffu, rs1, 1);
        rs1 += __shfl_xor_sync(0xffffffffu, rs1, 2);

        l0 = l0 * cr0 + rs0;
        l1 = l1 * cr1 + rs1;
        #pragma unroll
        for (int nt = 0; nt < 8; nt++) {
            O[nt][0] *= cr0; O[nt][1] *= cr0;
            O[nt][2] *= cr1; O[nt][3] *= cr1;
        }

        __syncthreads();   // all warps done reading Ks for scores

        // Store P (tf32) into Ps (= Ks region) for A-fragment reload.
        #pragma unroll
        for (int nt = 0; nt < 8; nt++) {
            float2 p0 = make_float2(__uint_as_float(tf32b(S[nt][0])),
                                    __uint_as_float(tf32b(S[nt][1])));
            float2 p1 = make_float2(__uint_as_float(tf32b(S[nt][2])),
                                    __uint_as_float(tf32b(S[nt][3])));
            *(float2*)&Ks[(wq + gid)     * AP + nt * 8 + 2 * tig] = p0;
            *(float2*)&Ks[(wq + gid + 8) * AP + nt * 8 + 2 * tig] = p1;
        }
        __syncthreads();

        // O += P V : ksteps over 64 keys, ntiles over 64 dims.
        #pragma unroll
        for (int ks = 0; ks < 8; ks++) {
            const int kb = ks * 8;
            uint32_t a0 = __float_as_uint(Ks[(wq + gid)     * AP + kb + tig]);
            uint32_t a1 = __float_as_uint(Ks[(wq + gid + 8) * AP + kb + tig]);
            uint32_t a2 = __float_as_uint(Ks[(wq + gid)     * AP + kb + tig + 4]);
            uint32_t a3 = __float_as_uint(Ks[(wq + gid + 8) * AP + kb + tig + 4]);
            #pragma unroll
            for (int nt = 0; nt < 8; nt++) {
                const int n = nt * 8 + gid;
                uint32_t b0 = __float_as_uint(Vs[(kb + tig)     * VP + n]);
                uint32_t b1 = __float_as_uint(Vs[(kb + tig + 4) * VP + n]);
                mma_tf32(O[nt], a0, a1, a2, a3, b0, b1);
            }
        }
    }

    // Epilogue: normalize, write Y rows (q0+wq+gid) and (+8).
    const float inv0 = 1.f / l0;
    const float inv1 = 1.f / l1;
    #pragma unroll
    for (int nt = 0; nt < 8; nt++) {
        const int cc = h * DKH + nt * 8 + 2 * tig;
        const size_t r0 = (size_t)b * TSEQ + q0 + wq + gid;
        float2 v0 = make_float2(O[nt][0] * inv0, O[nt][1] * inv0);
        float2 v1 = make_float2(O[nt][2] * inv1, O[nt][3] * inv1);
        *(float2*)(g_Y + r0 * D + cc)       = v0;
        *(float2*)(g_Y + (r0 + 8) * D + cc) = v1;
    }
}

// ---------------------------------------------------------------------------
extern "C" void kernel_launch(void* const* d_in, const int* in_sizes, int n_in,
                              void* d_out, int out_size)
{
    const float* X  = (const float*)d_in[0];
    const float* Wq = (const float*)d_in[1];
    const float* Wk = (const float*)d_in[2];
    const float* Wv = (const float*)d_in[3];
    const float* Wo = (const float*)d_in[4];
    float* out = (float*)d_out;

    cudaFuncSetAttribute(attn_mma,
                         cudaFuncAttributeMaxDynamicSharedMemorySize,
                         ATTN_SMEM_BYTES);

    dim3 gemm_grid(D / 128, MTOT / 128);   // (8, 64)
    mma_gemm<<<gemm_grid, 256>>>(X, Wq, nullptr, -1, 0);
    mma_gemm<<<gemm_grid, 256>>>(X, Wk, nullptr, -1, 1);
    mma_gemm<<<gemm_grid, 256>>>(X, Wv, nullptr, -1, 2);

    dim3 attn_grid(TSEQ / 64, NH, BSZ);    // (32, 16, 4)
    attn_mma<<<attn_grid, 128, ATTN_SMEM_BYTES>>>();

    mma_gemm<<<gemm_grid, 256>>>(nullptr, Wo, out, 3, -1);
}